// round 15
// baseline (speedup 1.0000x reference)
#include <cuda_runtime.h>
#include <math.h>

#define NB    2048
#define HID   64
#define TAU   22

__device__ float g_C[2][2][7];           // [graph][{C1,C2}][f]
__device__ float g_Mt[2][HID][TAU];      // [graph][k][t] = sum_m W2_g[k][m]*fc2W[m][t]

__device__ __forceinline__ float eluf(float x) { return x > 0.0f ? x : (__expf(x) - 1.0f); }

// ---------- setup: batch-invariant precompute ----------
__global__ void __launch_bounds__(128) k_setup(
    const float* __restrict__ uW1, const float* __restrict__ uA,
    const float* __restrict__ uW2,
    const float* __restrict__ dW1, const float* __restrict__ dA,
    const float* __restrict__ dW2,
    const float* __restrict__ fc2W)
{
    const int id = blockIdx.x * 128 + threadIdx.x;   // 45*128 = 5760 >= 28+5632
    if (id < 28) {
        int g = id / 14, rem = id % 14, which = rem / 7, f = rem % 7;
        const float* W1 = g ? dW1 : uW1;
        const float* A  = (g ? dA : uA) + which * HID;
        float acc = 0.0f;
        #pragma unroll 8
        for (int k = 0; k < HID; k++) acc = fmaf(W1[f * HID + k], A[k], acc);
        g_C[g][which][f] = acc;
    }
    const int id2 = id - 28;
    if (id2 >= 0 && id2 < 2 * HID * TAU * 2) {
        int entry = id2 >> 1, half = id2 & 1;
        int g = entry / (HID * TAU); entry -= g * HID * TAU;
        int k = entry / TAU, t = entry - k * TAU;
        const float* W2 = (g ? dW2 : uW2) + k * HID + half * 32;
        const float* F  = fc2W + half * 32 * TAU + t;
        float acc = 0.0f;
        #pragma unroll
        for (int i = 0; i < 8; i++) {
            float4 w4 = *(const float4*)(W2 + i * 4);
            acc = fmaf(w4.x, __ldg(F + (i * 4 + 0) * TAU), acc);
            acc = fmaf(w4.y, __ldg(F + (i * 4 + 1) * TAU), acc);
            acc = fmaf(w4.z, __ldg(F + (i * 4 + 2) * TAU), acc);
            acc = fmaf(w4.w, __ldg(F + (i * 4 + 3) * TAU), acc);
        }
        acc += __shfl_down_sync(0xffffffffu, acc, 1);
        if (half == 0) g_Mt[g][k][t] = acc;
    }
}

// ---------- main: TWO warps per (batch, graph); 256 threads = 2 batches ----------
__global__ void __launch_bounds__(256) gat_main(
    const float* __restrict__ fp,
    const float* __restrict__ uW1, const float* __restrict__ dW1,
    const float* __restrict__ fc2b,
    float* __restrict__ out)
{
    __shared__ __align__(16) float feat[4][1280];   // 20 KB
    __shared__ float Wvs[4][HID];
    __shared__ float zy[4][2][8];                   // per-unit {z, Y0..Y6} per half
    __shared__ float part[8][TAU];

    const int tid  = threadIdx.x;
    const int w    = tid >> 5;          // 0..7
    const int lane = tid & 31;
    const int unit = w >> 1;            // 0..3 : (batch_local, graph)
    const int half = w & 1;             // node half: 0 -> nodes 0..63, 1 -> 64..127
    const int g    = unit & 1;
    const int b    = blockIdx.x * 2 + (unit >> 1);

    // 1) issue this half's feature loads (5 x LDG.128, coalesced)
    const float4* src = (const float4*)(fp + (long long)b * 2560 + g * 1280);
    float4 v[5];
    #pragma unroll
    for (int i = 0; i < 5; i++) v[i] = src[half * 160 + i * 32 + lane];

    // 2) coefficients + this lane's single W1 column (L1-hot; overlaps with loads)
    const float* W1  = g ? dW1 : uW1;
    const int    myk = half * 32 + lane;
    float Cc[7], Ct[7], w1k[7];
    #pragma unroll
    for (int f = 0; f < 7; f++) {
        Cc[f]  = __ldg(&g_C[g][0][f]);
        Ct[f]  = __ldg(&g_C[g][1][f]);
        w1k[f] = __ldg(&W1[f * HID + myk]);
    }

    // 3) stage this half's features (this warp later reads exactly this range)
    {
        float4* dst = (float4*)feat[unit];
        #pragma unroll
        for (int i = 0; i < 5; i++) dst[half * 160 + i * 32 + lane] = v[i];
    }
    // pair barrier: makes half-0's stores (incl. center row) visible to half-1
    asm volatile("bar.sync %0, 64;" :: "r"(unit + 1) : "memory");

    // 4) center features via uniform LDS broadcast; s0 computed per-lane
    float x0[7];
    {
        float2 q0 = *(const float2*)&feat[unit][0];
        float2 q1 = *(const float2*)&feat[unit][2];
        float2 q2 = *(const float2*)&feat[unit][4];
        x0[0] = q0.x; x0[1] = q0.y; x0[2] = q1.x; x0[3] = q1.y;
        x0[4] = q2.x; x0[5] = q2.y; x0[6] = feat[unit][6];
    }
    float s0 = 0.0f;
    #pragma unroll
    for (int f = 0; f < 7; f++) s0 = fmaf(x0[f], Cc[f], s0);

    // 5) owned nodes {64*half + lane, 64*half + 32 + lane}
    float x[2][7];
    #pragma unroll
    for (int n = 0; n < 2; n++) {
        const float* r = &feat[unit][(half * 64 + n * 32 + lane) * 10];
        float2 p0 = *(const float2*)(r);
        float2 p1 = *(const float2*)(r + 2);
        float2 p2 = *(const float2*)(r + 4);
        x[n][0] = p0.x; x[n][1] = p0.y;
        x[n][2] = p1.x; x[n][3] = p1.y;
        x[n][4] = p2.x; x[n][5] = p2.y;
        x[n][6] = r[6];
    }

    // 6) logits + exp (shift-free softmax; |logits| ~ O(1), overflow impossible)
    float p[2], z = 0.0f;
    #pragma unroll
    for (int n = 0; n < 2; n++) {
        float t = 0.0f;
        #pragma unroll
        for (int f = 0; f < 7; f++) t = fmaf(x[n][f], Ct[f], t);
        float vv = s0 + t;
        vv = vv > 0.0f ? vv : 0.2f * vv;
        if (n == 0 && half == 0 && lane == 0) vv = -1e30f;   // mask center
        p[n] = __expf(vv);
        z += p[n];
    }

    // 7) warp-reduce z and Y[f] = sum_j p_j x_j[f] over this half
    float Y[7];
    #pragma unroll
    for (int f = 0; f < 7; f++) Y[f] = p[0] * x[0][f] + p[1] * x[1][f];
    #pragma unroll
    for (int o = 16; o; o >>= 1) {
        z += __shfl_xor_sync(0xffffffffu, z, o);
        #pragma unroll
        for (int f = 0; f < 7; f++)
            Y[f] += __shfl_xor_sync(0xffffffffu, Y[f], o);
    }
    // pair combine via smem (lane 0 writes 8 scalars; barrier; uniform reads)
    if (lane == 0) {
        zy[unit][half][0] = z;
        #pragma unroll
        for (int f = 0; f < 7; f++) zy[unit][half][1 + f] = Y[f];
    }
    asm volatile("bar.sync %0, 64;" :: "r"(unit + 1) : "memory");
    z = zy[unit][0][0] + zy[unit][1][0];
    #pragma unroll
    for (int f = 0; f < 7; f++) Y[f] = zy[unit][0][1 + f] + zy[unit][1][1 + f];
    const float zi = 1.0f / z;

    // 8) Wv[myk] = elu(x0.W1[:,myk]) + 127*elu((Y/z).W1[:,myk])
    {
        float ca = 0.0f, la = 0.0f;
        #pragma unroll
        for (int f = 0; f < 7; f++) {
            ca = fmaf(Y[f] * zi, w1k[f], ca);
            la = fmaf(x0[f],     w1k[f], la);
        }
        Wvs[unit][myk] = eluf(la) + 127.0f * eluf(ca);
    }
    __syncwarp();

    // 9) head partial over this half's 32 k's: part[w][t] = sum_k Wv[k]*Mt[g][k][t]
    //    (reads only this warp's own Wvs writes; coalesced L1-hot LDG)
    if (lane < TAU) {
        const int k0 = half * 32;
        float a0 = 0.0f, a1 = 0.0f;
        #pragma unroll
        for (int k = 0; k < 16; k++) {
            a0 = fmaf(Wvs[unit][k0 + k],      __ldg(&g_Mt[g][k0 + k][lane]),      a0);
            a1 = fmaf(Wvs[unit][k0 + 16 + k], __ldg(&g_Mt[g][k0 + 16 + k][lane]), a1);
        }
        part[w][lane] = a0 + a1;
    }
    __syncthreads();

    // 10) combine 4 partials per batch (u0+u1+d0+d1), bias, relu-clip, store
    if (tid < 2 * TAU) {
        const int bb = (tid >= TAU);
        const int t  = tid - bb * TAU;
        float acc = part[4 * bb][t] + part[4 * bb + 1][t]
                  + part[4 * bb + 2][t] + part[4 * bb + 3][t] + __ldg(&fc2b[t]);
        acc = fminf(fmaxf(acc, 0.0f), 10.0f);
        out[((long long)(blockIdx.x * 2 + bb)) * TAU + t] = acc;
    }
}

extern "C" void kernel_launch(void* const* d_in, const int* in_sizes, int n_in,
                              void* d_out, int out_size)
{
    const float* fp    = (const float*)d_in[0];
    const float* uW1   = (const float*)d_in[1];
    const float* uA    = (const float*)d_in[2];
    const float* uW2   = (const float*)d_in[3];
    // d_in[4] = u_out_a : provably unused (singleton/uniform layer-2 softmax)
    const float* dW1   = (const float*)d_in[5];
    const float* dA    = (const float*)d_in[6];
    const float* dW2   = (const float*)d_in[7];
    // d_in[8] = d_out_a : unused
    const float* fc2W  = (const float*)d_in[9];
    const float* fc2b  = (const float*)d_in[10];
    float* out = (float*)d_out;

    k_setup<<<45, 128>>>(uW1, uA, uW2, dW1, dA, dW2, fc2W);
    gat_main<<<NB / 2, 256>>>(fp, uW1, dW1, fc2b, out);
}